// round 13
// baseline (speedup 1.0000x reference)
#include <cuda_runtime.h>
#include <cuda_fp16.h>

#define NMAX 50000
#define EMAX 800000
// D = 128, ED = 64, H = 4, U = 32, HU = 128

// ---- scratch (device globals) ----
__device__ float  g_q  [NMAX * 128];
__device__ __half g_kh [NMAX * 128];
__device__ __half g_vh [NMAX * 128];
__device__ __half g_mkh[NMAX * 256];     // Mk[n][h*64 + c], fp16
__device__ float  g_kb [NMAX * 4];       // kb[n][h]
__device__ int    g_rowptr[NMAX + 1];
__device__ float  g_scores[EMAX * 4];    // scores[e][h]

// ============================================================================
// K1: q,k,v = X @ W{q,k,v} + b — [N,128]@[128,128], blockIdx.y selects matrix.
//     Register-prefetch pipelined: next tile's global loads issue before the
//     FFMA block so DRAM latency hides under compute.
// ============================================================================
__global__ __launch_bounds__(256) void qkv_gemm_kernel(
    const float* __restrict__ X,
    const float* __restrict__ Wq, const float* __restrict__ bq,
    const float* __restrict__ Wk, const float* __restrict__ bk,
    const float* __restrict__ Wv, const float* __restrict__ bv,
    int N)
{
    __shared__ float As[32][129];
    __shared__ float Bs[32][128];

    const float* W; const float* bias;
    if (blockIdx.y == 0)      { W = Wq; bias = bq; }
    else if (blockIdx.y == 1) { W = Wk; bias = bk; }
    else                      { W = Wv; bias = bv; }
    const bool isQ = (blockIdx.y == 0);
    __half* OutH = (blockIdx.y == 1) ? g_kh : g_vh;

    const int row0 = blockIdx.x * 128;
    const int tid  = threadIdx.x;
    const int tx   = tid & 15;
    const int ty   = tid >> 4;

    // load indices
    const int ar = (tid >> 3);          // +i*32
    const int ac = (tid & 7) * 4;
    const int bk_ = (tid >> 5);         // +i*8
    const int bn  = (tid & 31) * 4;

    float4 ra[4], rb[4];
#pragma unroll
    for (int i = 0; i < 4; i++) {
        const int r = ar + i * 32;
        ra[i] = make_float4(0.f, 0.f, 0.f, 0.f);
        if (row0 + r < N)
            ra[i] = *(const float4*)(X + (size_t)(row0 + r) * 128 + ac);
        rb[i] = *(const float4*)(W + (size_t)(bk_ + i * 8) * 128 + bn);
    }

    float acc[8][8];
#pragma unroll
    for (int i = 0; i < 8; i++)
#pragma unroll
        for (int j = 0; j < 8; j++) acc[i][j] = 0.f;

#pragma unroll
    for (int t = 0; t < 4; t++) {
        // store prefetched tile to smem
#pragma unroll
        for (int i = 0; i < 4; i++) {
            const int r = ar + i * 32;
            As[ac + 0][r] = ra[i].x;
            As[ac + 1][r] = ra[i].y;
            As[ac + 2][r] = ra[i].z;
            As[ac + 3][r] = ra[i].w;
            *(float4*)&Bs[bk_ + i * 8][bn] = rb[i];
        }
        __syncthreads();

        // prefetch next tile (latency hidden under compute below)
        if (t < 3) {
            const int kt = (t + 1) * 32;
#pragma unroll
            for (int i = 0; i < 4; i++) {
                const int r = ar + i * 32;
                ra[i] = make_float4(0.f, 0.f, 0.f, 0.f);
                if (row0 + r < N)
                    ra[i] = *(const float4*)(X + (size_t)(row0 + r) * 128 + kt + ac);
                rb[i] = *(const float4*)(W + (size_t)(kt + bk_ + i * 8) * 128 + bn);
            }
        }

#pragma unroll
        for (int k = 0; k < 32; k++) {
            float a[8], b[8];
#pragma unroll
            for (int i = 0; i < 8; i++) a[i] = As[k][tx * 8 + i];
            *(float4*)&b[0] = *(float4*)&Bs[k][ty * 8];
            *(float4*)&b[4] = *(float4*)&Bs[k][ty * 8 + 4];
#pragma unroll
            for (int i = 0; i < 8; i++)
#pragma unroll
                for (int j = 0; j < 8; j++)
                    acc[i][j] = fmaf(a[i], b[j], acc[i][j]);
        }
        __syncthreads();
    }

#pragma unroll
    for (int i = 0; i < 8; i++) {
        int r = row0 + tx * 8 + i;
        if (r < N) {
            float o[8];
#pragma unroll
            for (int j = 0; j < 8; j++) o[j] = acc[i][j] + bias[ty * 8 + j];
            if (isQ) {
                *(float4*)(g_q + (size_t)r * 128 + ty * 8)     = make_float4(o[0], o[1], o[2], o[3]);
                *(float4*)(g_q + (size_t)r * 128 + ty * 8 + 4) = make_float4(o[4], o[5], o[6], o[7]);
            } else {
                __half2 h[4];
                h[0] = __float22half2_rn(make_float2(o[0], o[1]));
                h[1] = __float22half2_rn(make_float2(o[2], o[3]));
                h[2] = __float22half2_rn(make_float2(o[4], o[5]));
                h[3] = __float22half2_rn(make_float2(o[6], o[7]));
                *(uint4*)(OutH + (size_t)r * 128 + ty * 8) = *(uint4*)h;
            }
        }
    }
}

// ============================================================================
// K2: Mk[n,h,c] = sum_u We[c, h*32+u] * k[n,h,u] (fp16 out);
//     kb[n,h] = sum_u be[hu]*k[n,h,u]
// ============================================================================
__global__ __launch_bounds__(256) void mk_kernel(
    const float* __restrict__ We, const float* __restrict__ be, int N)
{
    __shared__ float WeT[128][65];
    __shared__ float ks[16][128];

    const int tid = threadIdx.x;
    const int n0  = blockIdx.x * 16;

    for (int i = tid; i < 64 * 128; i += 256) {
        int c  = i >> 7;
        int hu = i & 127;
        WeT[hu][c] = We[i];
    }
    for (int i = tid; i < 16 * 64; i += 256) {
        int nl  = i >> 6;
        int off = (i & 63) * 2;
        __half2 hv = __half2half2(__float2half(0.f));
        if (n0 + nl < N) hv = *(const __half2*)(g_kh + (size_t)(n0 + nl) * 128 + off);
        float2 f = __half22float2(hv);
        ks[nl][off]     = f.x;
        ks[nl][off + 1] = f.y;
    }
    __syncthreads();

    const int h = tid >> 6, c = tid & 63;
#pragma unroll 1
    for (int nl = 0; nl < 16; nl++) {
        if (n0 + nl >= N) break;
        float s = 0.f;
#pragma unroll
        for (int u = 0; u < 32; u++)
            s = fmaf(ks[nl][h * 32 + u], WeT[h * 32 + u][c], s);
        g_mkh[(size_t)(n0 + nl) * 256 + h * 64 + c] = __float2half_rn(s);
    }
    if (tid < 64) {
        int nl = tid >> 2, h2 = tid & 3;
        if (n0 + nl < N) {
            float s = 0.f;
#pragma unroll
            for (int u = 0; u < 32; u++)
                s = fmaf(be[h2 * 32 + u], ks[nl][h2 * 32 + u], s);
            g_kb[(size_t)(n0 + nl) * 4 + h2] = s;
        }
    }
}

// ============================================================================
// K3: rowptr[n] = lower_bound(src, n)  (src sorted)
// ============================================================================
__global__ void rowptr_kernel(const int* __restrict__ src, int E, int N)
{
    int n = blockIdx.x * blockDim.x + threadIdx.x;
    if (n > N) return;
    int lo = 0, hi = E;
    while (lo < hi) {
        int mid = (lo + hi) >> 1;
        if (src[mid] < n) lo = mid + 1; else hi = mid;
    }
    g_rowptr[n] = lo;
}

// ============================================================================
// K4a: score kernel v3 — ALL gathers line-coherent (unchanged from best).
// ============================================================================
__global__ __launch_bounds__(256) void score_kernel(
    const float* __restrict__ EF,
    const int* __restrict__ src, const int* __restrict__ dst, int E)
{
    __shared__ float sEF[8][256];   // 8 warps x (4 edges x 64 floats)

    const int tid  = threadIdx.x;
    const int lane = tid & 31;
    const int warp = tid >> 5;
    const int ebase = (blockIdx.x * 8 + warp) * 4;

#pragma unroll
    for (int j = 0; j < 2; j++) {
        const int f = j * 32 + lane;
        const int ee = ebase + (f >> 4);
        if (ee < E) {
            const float4 v = __ldcs((const float4*)(EF + (size_t)ee * 64) + (f & 15));
            *(float4*)&sEF[warp][f * 4] = v;
        }
    }
    __syncwarp();

    const int g  = lane >> 3;
    const int sl = lane & 7;
    int e = ebase + g;
    const bool valid = (e < E);
    if (!valid) e = E - 1;

    const int n = src[e];
    const int d = dst[e];

    float ef0x, ef0y, ef0z, ef0w, ef1x, ef1y, ef1z, ef1w;
    {
        const float4 a = *(const float4*)&sEF[warp][g * 64 + sl * 8];
        const float4 b = *(const float4*)&sEF[warp][g * 64 + sl * 8 + 4];
        ef0x = a.x; ef0y = a.y; ef0z = a.z; ef0w = a.w;
        ef1x = b.x; ef1y = b.y; ef1z = b.z; ef1w = b.w;
    }

    float t0 = 0.f, t1 = 0.f, t2 = 0.f, t3 = 0.f;

    {
        const uint4* mkp = (const uint4*)(g_mkh + (size_t)d * 256);
        const uint4 m0 = mkp[0 * 8 + sl];
        const uint4 m1 = mkp[1 * 8 + sl];
        const uint4 m2 = mkp[2 * 8 + sl];
        const uint4 m3 = mkp[3 * 8 + sl];
        float2 a;
#define DOT8(T, M)                                                              \
        a = __half22float2(*(const __half2*)&(M).x); T = fmaf(ef0x, a.x, T); T = fmaf(ef0y, a.y, T); \
        a = __half22float2(*(const __half2*)&(M).y); T = fmaf(ef0z, a.x, T); T = fmaf(ef0w, a.y, T); \
        a = __half22float2(*(const __half2*)&(M).z); T = fmaf(ef1x, a.x, T); T = fmaf(ef1y, a.y, T); \
        a = __half22float2(*(const __half2*)&(M).w); T = fmaf(ef1z, a.x, T); T = fmaf(ef1w, a.y, T);
        DOT8(t0, m0)
        DOT8(t1, m1)
        DOT8(t2, m2)
        DOT8(t3, m3)
#undef DOT8
    }

    {
        const float* qrow = g_q  + (size_t)n * 128;
        const __half* krow = g_kh + (size_t)d * 128;
        float2 a;
#define QK4(T, I)                                                               \
        {                                                                       \
            const float4 qq = *(const float4*)(qrow + (I) * 32 + sl * 4);       \
            const uint2  kk = *(const uint2*) (krow + (I) * 32 + sl * 4);       \
            a = __half22float2(*(const __half2*)&kk.x);                         \
            T = fmaf(qq.x, a.x, T); T = fmaf(qq.y, a.y, T);                     \
            a = __half22float2(*(const __half2*)&kk.y);                         \
            T = fmaf(qq.z, a.x, T); T = fmaf(qq.w, a.y, T);                     \
        }
        QK4(t0, 0)
        QK4(t1, 1)
        QK4(t2, 2)
        QK4(t3, 3)
#undef QK4
    }

#pragma unroll
    for (int o = 1; o <= 4; o <<= 1) {
        t0 += __shfl_xor_sync(0xffffffffu, t0, o);
        t1 += __shfl_xor_sync(0xffffffffu, t1, o);
        t2 += __shfl_xor_sync(0xffffffffu, t2, o);
        t3 += __shfl_xor_sync(0xffffffffu, t3, o);
    }

    if (valid && sl < 4) {
        const float th = (sl == 0) ? t0 : (sl == 1) ? t1 : (sl == 2) ? t2 : t3;
        g_scores[(size_t)e * 4 + sl] = th + g_kb[(size_t)d * 4 + sl];
    }
}

// ============================================================================
// K4b: aggregate kernel v2 — TWO-PASS softmax.
//   Pass 1: coalesced max sweep over scores (8 edges/instr) + 3 shfl-max.
//   Pass 2: w=exp(s-m); sexp+=w; acc+=w*v — NO serial rescale chain.
// ============================================================================
__global__ __launch_bounds__(256) void aggregate_kernel(
    const int* __restrict__ dst,
    const float* __restrict__ Wo, const float* __restrict__ bo,
    float* __restrict__ out, int N)
{
    __shared__ float sWo[128 * 32];
    __shared__ float sbo[32];
    const int tid = threadIdx.x;
    for (int i = tid; i < 1024; i += 256)
        ((float4*)sWo)[i] = ((const float4*)Wo)[i];
    if (tid < 32) sbo[tid] = bo[tid];
    __syncthreads();

    const int lane = tid & 31, warp = tid >> 5;
    const int n = blockIdx.x * 8 + warp;
    if (n >= N) return;

    const int hl = lane >> 3;
    const int e0 = g_rowptr[n], e1 = g_rowptr[n + 1];

    // ---- pass 1: per-head max, coalesced over scores[e0*4 .. e1*4) ----
    float mx = -1e30f;
    for (int idx = e0 * 4 + lane; idx < e1 * 4; idx += 32)
        mx = fmaxf(mx, g_scores[idx]);
    // reduce over lanes sharing (lane & 3) == head
    mx = fmaxf(mx, __shfl_xor_sync(0xffffffffu, mx, 4));
    mx = fmaxf(mx, __shfl_xor_sync(0xffffffffu, mx, 8));
    mx = fmaxf(mx, __shfl_xor_sync(0xffffffffu, mx, 16));
    const float m = __shfl_sync(0xffffffffu, mx, hl);   // lane hl holds head hl

    // ---- pass 2: independent accumulation ----
    float  sexp = 0.f;
    float4 acc  = make_float4(0.f, 0.f, 0.f, 0.f);

    int e = e0;
#pragma unroll 1
    for (; e + 4 <= e1; e += 4) {
        const int d0 = dst[e],     d1 = dst[e + 1];
        const int d2 = dst[e + 2], d3 = dst[e + 3];
        const float s0 = g_scores[(size_t)(e    ) * 4 + hl];
        const float s1 = g_scores[(size_t)(e + 1) * 4 + hl];
        const float s2 = g_scores[(size_t)(e + 2) * 4 + hl];
        const float s3 = g_scores[(size_t)(e + 3) * 4 + hl];
        const uint2 r0 = *(const uint2*)(g_vh + (size_t)d0 * 128 + lane * 4);
        const uint2 r1 = *(const uint2*)(g_vh + (size_t)d1 * 128 + lane * 4);
        const uint2 r2 = *(const uint2*)(g_vh + (size_t)d2 * 128 + lane * 4);
        const uint2 r3 = *(const uint2*)(g_vh + (size_t)d3 * 128 + lane * 4);

        const float w0 = __expf(s0 - m);
        const float w1 = __expf(s1 - m);
        const float w2 = __expf(s2 - m);
        const float w3 = __expf(s3 - m);
        sexp += (w0 + w1) + (w2 + w3);

        float2 p0 = __half22float2(*(const __half2*)&r0.x);
        float2 p1 = __half22float2(*(const __half2*)&r1.x);
        float2 p2 = __half22float2(*(const __half2*)&r2.x);
        float2 p3 = __half22float2(*(const __half2*)&r3.x);
        acc.x += fmaf(w0, p0.x, w1 * p1.x) + fmaf(w2, p2.x, w3 * p3.x);
        acc.y += fmaf(w0, p0.y, w1 * p1.y) + fmaf(w2, p2.y, w3 * p3.y);
        p0 = __half22float2(*(const __half2*)&r0.y);
        p1 = __half22float2(*(const __half2*)&r1.y);
        p2 = __half22float2(*(const __half2*)&r2.y);
        p3 = __half22float2(*(const __half2*)&r3.y);
        acc.z += fmaf(w0, p0.x, w1 * p1.x) + fmaf(w2, p2.x, w3 * p3.x);
        acc.w += fmaf(w0, p0.y, w1 * p1.y) + fmaf(w2, p2.y, w3 * p3.y);
    }
#pragma unroll 1
    for (; e < e1; e++) {
        const int d0 = dst[e];
        const float s0 = g_scores[(size_t)e * 4 + hl];
        const uint2 r0 = *(const uint2*)(g_vh + (size_t)d0 * 128 + lane * 4);
        const float w0 = __expf(s0 - m);
        sexp += w0;
        const float2 p0 = __half22float2(*(const __half2*)&r0.x);
        const float2 p1 = __half22float2(*(const __half2*)&r0.y);
        acc.x = fmaf(w0, p0.x, acc.x);
        acc.y = fmaf(w0, p0.y, acc.y);
        acc.z = fmaf(w0, p1.x, acc.z);
        acc.w = fmaf(w0, p1.y, acc.w);
    }

    const float inv = (sexp > 0.f) ? (1.0f / sexp) : 0.f;
    acc.x *= inv; acc.y *= inv; acc.z *= inv; acc.w *= inv;

    float o = sbo[lane];
#pragma unroll
    for (int p = 0; p < 32; p++) {
        const float ax = __shfl_sync(0xffffffffu, acc.x, p);
        const float ay = __shfl_sync(0xffffffffu, acc.y, p);
        const float az = __shfl_sync(0xffffffffu, acc.z, p);
        const float aw = __shfl_sync(0xffffffffu, acc.w, p);
        o = fmaf(ax, sWo[(4 * p + 0) * 32 + lane], o);
        o = fmaf(ay, sWo[(4 * p + 1) * 32 + lane], o);
        o = fmaf(az, sWo[(4 * p + 2) * 32 + lane], o);
        o = fmaf(aw, sWo[(4 * p + 3) * 32 + lane], o);
    }
    out[(size_t)n * 32 + lane] = fmaxf(o, 0.f);
}

// ============================================================================
// launch
// ============================================================================
extern "C" void kernel_launch(void* const* d_in, const int* in_sizes, int n_in,
                              void* d_out, int out_size)
{
    const float* X  = (const float*)d_in[0];
    const int*   EI = (const int*)  d_in[1];   // [2,E]: src then dst
    const float* EF = (const float*)d_in[2];
    const float* Wq = (const float*)d_in[3];
    const float* bq = (const float*)d_in[4];
    const float* Wk = (const float*)d_in[5];
    const float* bk = (const float*)d_in[6];
    const float* Wv = (const float*)d_in[7];
    const float* bv = (const float*)d_in[8];
    const float* We = (const float*)d_in[9];
    const float* be = (const float*)d_in[10];
    const float* Wo = (const float*)d_in[11];
    const float* bo = (const float*)d_in[12];

    const int N = in_sizes[0] / 128;
    const int E = in_sizes[1] / 2;

    dim3 g1((N + 127) / 128, 3);
    qkv_gemm_kernel<<<g1, 256>>>(X, Wq, bq, Wk, bk, Wv, bv, N);
    mk_kernel<<<(N + 15) / 16, 256>>>(We, be, N);
    rowptr_kernel<<<(N + 1 + 255) / 256, 256>>>(EI, E, N);
    score_kernel<<<(E + 31) / 32, 256>>>(EF, EI, EI + E, E);
    aggregate_kernel<<<(N + 7) / 8, 256>>>(EI + E, Wo, bo, (float*)d_out, N);
}